// round 13
// baseline (speedup 1.0000x reference)
#include <cuda_runtime.h>
#include <math.h>
#include <stdint.h>

#define H 2048
#define E 64
#define S 4096
#define B 2
#define SW 1024
#define NEGF (-3.4028234663852886e38f)   // -FLT_MAX == finfo(float32).min

#define OFF_SLID 33554432ull             // 2*4096*4096
#define OFF_W    67108864ull
#define OFF_I    67141632ull             // OFF_W + 8192*4

#define RSQRT_H 0.022097086912079608f    // 1/sqrt(2048)
#define KT 32                            // k-tile
#define PAD 68                           // X row stride (floats)
#define WPAD 132                         // W dup row stride (floats)
#define NKT (H / KT)                     // 64
#define XTILE_F (KT * PAD)               // 2176
#define WTILE_F (KT * WPAD)              // 4224
#define GRP_F (2 * XTILE_F + 2 * WTILE_F)   // 12800 floats per warpgroup
#define GATE_SMEM_BYTES (2 * GRP_F * 4)     // 102400 B
#define GATE_BLOCKS 128

// scratch (no allocations allowed)
__device__ int4  g_qmeta[B * S];                        // {flo, s1lo, v2lo, v2hi}
__device__ __align__(16) float g_w2t[NKT * WTILE_F];    // folded W, dup-interleaved

// ---------------------------------------------------------------------------
// cp.async helpers
// ---------------------------------------------------------------------------
#define CP_ASYNC4(dst, src) \
    asm volatile("cp.async.ca.shared.global [%0], [%1], 4;" :: "r"(dst), "l"(src))
#define CP_ASYNC16(dst, src) \
    asm volatile("cp.async.cg.shared.global [%0], [%1], 16;" :: "r"(dst), "l"(src))
#define CP_COMMIT() asm volatile("cp.async.commit_group;")
#define CP_WAIT1()  asm volatile("cp.async.wait_group 1;")

// packed fp32x2 FMA (sm_100+)
__device__ __forceinline__ void ffma2(unsigned long long& d,
                                      unsigned long long a,
                                      unsigned long long b) {
    asm("fma.rn.f32x2 %0, %1, %2, %0;" : "+l"(d) : "l"(a), "l"(b));
}

// ---------------------------------------------------------------------------
// K0: fold scale & H^-0.5 into W; dup-interleaved k-major tile images.
// Row layout (132 floats): [0,64):  lane tc gets {w(4tc),w(4tc),w(4tc+1),w(4tc+1)} at tc*4
//                          [64,128): lane tc gets {w(4tc+2),w(4tc+2),w(4tc+3),w(4tc+3)} at 64+tc*4
// ---------------------------------------------------------------------------
__global__ __launch_bounds__(256) void fold_kernel(const float* __restrict__ scale,
                                                   const float* __restrict__ pw) {
    int i = blockIdx.x * 1024 + threadIdx.x * 4;     // over E*H = 131072
    float4 pw4 = *(const float4*)(pw + i);
    float4 sc4 = *(const float4*)(scale + (i & (H - 1)));
    int e  = i >> 11;
    int h  = i & (H - 1);
    int kt = h >> 5, k = h & 31;                     // k % 4 == 0
    int tc = e >> 2, r = e & 3;
    int base = (r < 2) ? (tc * 4 + 2 * r) : (64 + tc * 4 + 2 * (r - 2));
    float v0 = pw4.x * sc4.x * RSQRT_H;
    float v1 = pw4.y * sc4.y * RSQRT_H;
    float v2 = pw4.z * sc4.z * RSQRT_H;
    float v3 = pw4.w * sc4.w * RSQRT_H;
    float* dst = g_w2t + kt * WTILE_F + k * WPAD + base;
    *(float2*)(dst + 0 * WPAD) = make_float2(v0, v0);
    *(float2*)(dst + 1 * WPAD) = make_float2(v1, v1);
    *(float2*)(dst + 2 * WPAD) = make_float2(v2, v2);
    *(float2*)(dst + 3 * WPAD) = make_float2(v3, v3);
}

// ---------------------------------------------------------------------------
// 512-thread block scans for prep (16 warps, 8 elems/thread)
// ---------------------------------------------------------------------------
__device__ __forceinline__ int blk_excl_max512(int agg, int t, int* sc) {
    int lane = t & 31, w = t >> 5;
    int inc = agg;
    #pragma unroll
    for (int o = 1; o < 32; o <<= 1) {
        int u = __shfl_up_sync(0xffffffffu, inc, o);
        if (lane >= o) inc = max(inc, u);
    }
    if (lane == 31) sc[w] = inc;
    __syncthreads();
    int wex = -0x7fffffff;
    for (int i = 0; i < w; i++) wex = max(wex, sc[i]);
    int lex = __shfl_up_sync(0xffffffffu, inc, 1);
    if (lane == 0) lex = -0x7fffffff;
    __syncthreads();
    return max(wex, lex);
}

__device__ __forceinline__ int blk_excl_min_bwd512(int agg, int t, int* sc) {
    int lane = t & 31, w = t >> 5;
    int inc = agg;
    #pragma unroll
    for (int o = 1; o < 32; o <<= 1) {
        int u = __shfl_down_sync(0xffffffffu, inc, o);
        if (lane < 32 - o) inc = min(inc, u);
    }
    if (lane == 0) sc[w] = inc;
    __syncthreads();
    int wex = 0x7fffffff;
    for (int i = w + 1; i < 16; i++) wex = min(wex, sc[i]);
    int lex = __shfl_down_sync(0xffffffffu, inc, 1);
    if (lane == 31) lex = 0x7fffffff;
    __syncthreads();
    return min(wex, lex);
}

// ---------------------------------------------------------------------------
// K1: blocks [0,128): split-K gate; blocks [128,130): prep on idle SMs
// ---------------------------------------------------------------------------
__global__ __launch_bounds__(512) void gate_prep_kernel(const float* __restrict__ x,
                                                        const int* __restrict__ packed,
                                                        const int* __restrict__ mm,
                                                        float* __restrict__ out) {
    extern __shared__ __align__(16) float dsm[];
    __shared__ float ssq2[64];
    __shared__ int sc[16];

    int tid = threadIdx.x;

    if (blockIdx.x < GATE_BLOCKS) {
        // ================= GATE (split-K) =================
        int g = tid >> 8;                 // warpgroup: 0 or 1
        int t = tid & 255;
        int w = t >> 5, lane = t & 31;
        int tr = t >> 4, tc = t & 15;
        const float* xb = x + (size_t)blockIdx.x * 64 * H;

        // group layout: [X0, X1, W0, W1]
        float* grp = dsm + g * GRP_F;
        uint32_t gbase = (uint32_t)__cvta_generic_to_shared(grp);
        const uint32_t XST = (uint32_t)(XTILE_F * 4);
        const uint32_t WST = (uint32_t)(WTILE_F * 4);
        uint32_t wbase = gbase + 2 * XST;

        uint32_t xdst0 = gbase + (uint32_t)(lane * PAD + w) * 4u;
        const float* xsrc0 = xb + (size_t)w * H + g * (H / 2) + lane;
        const float* wimg = g_w2t + (size_t)g * (NKT / 2) * WTILE_F;

        // prologue: local tile 0 into stage 0
        {
            #pragma unroll
            for (int i = 0; i < 8; i++)
                CP_ASYNC4(xdst0 + (uint32_t)(8 * i) * 4u, xsrc0 + (size_t)(8 * i) * H);
            const float4* wsrc = (const float4*)(wimg);
            #pragma unroll
            for (int j = 0; j < 4; j++)
                CP_ASYNC16(wbase + (uint32_t)(t + j * 256) * 16u, wsrc + t + j * 256);
            if (t < 32)
                CP_ASYNC16(wbase + (uint32_t)(t + 1024) * 16u, wsrc + t + 1024);
            CP_COMMIT();
        }

        unsigned long long acc[4][2] = {};   // [expert j][row pair p]
        float ssq[8] = {};

        for (int kt = 0; kt < NKT / 2; kt++) {
            int s = kt & 1;
            if (kt + 1 < NKT / 2) {
                int ns = (kt + 1) & 1;
                uint32_t xd = xdst0 + (uint32_t)ns * XST;
                const float* xs = xsrc0 + (size_t)(kt + 1) * KT;
                #pragma unroll
                for (int i = 0; i < 8; i++)
                    CP_ASYNC4(xd + (uint32_t)(8 * i) * 4u, xs + (size_t)(8 * i) * H);
                const float4* wsrc = (const float4*)(wimg + (size_t)(kt + 1) * WTILE_F);
                uint32_t wd = wbase + (uint32_t)ns * WST;
                #pragma unroll
                for (int j = 0; j < 4; j++)
                    CP_ASYNC16(wd + (uint32_t)(t + j * 256) * 16u, wsrc + t + j * 256);
                if (t < 32)
                    CP_ASYNC16(wd + (uint32_t)(t + 1024) * 16u, wsrc + t + 1024);
            }
            CP_COMMIT();
            CP_WAIT1();
            __syncthreads();

            const float* Xs = grp + s * XTILE_F;
            const float* Ws = grp + 2 * XTILE_F + s * WTILE_F;
            #pragma unroll
            for (int k = 0; k < KT; k++) {
                ulonglong2 xp = *(const ulonglong2*)(Xs + k * PAD + 4 * tr);      // {x0,x1},{x2,x3}
                ulonglong2 wA = *(const ulonglong2*)(Ws + k * WPAD + 4 * tc);     // {w0,w0},{w1,w1}
                ulonglong2 wB = *(const ulonglong2*)(Ws + k * WPAD + 64 + 4 * tc);// {w2,w2},{w3,w3}
                ffma2(acc[0][0], xp.x, wA.x); ffma2(acc[0][1], xp.y, wA.x);
                ffma2(acc[1][0], xp.x, wA.y); ffma2(acc[1][1], xp.y, wA.y);
                ffma2(acc[2][0], xp.x, wB.x); ffma2(acc[2][1], xp.y, wB.x);
                ffma2(acc[3][0], xp.x, wB.y); ffma2(acc[3][1], xp.y, wB.y);
            }
            // rms sum-of-squares pass (lane = k, rows w+8i) over this K half
            #pragma unroll
            for (int i = 0; i < 8; i++) {
                float v = Xs[lane * PAD + (w + 8 * i)];
                ssq[i] = fmaf(v, v, ssq[i]);
            }
            __syncthreads();
        }

        // write this group's partial logits into its X region (pipeline done)
        float (*s_lg)[PAD] = (float (*)[PAD])grp;
        #pragma unroll
        for (int j = 0; j < 4; j++) {
            #pragma unroll
            for (int p = 0; p < 2; p++) {
                float lo, hi;
                asm("mov.b64 {%0,%1},%2;" : "=f"(lo), "=f"(hi) : "l"(acc[j][p]));
                s_lg[4 * tr + 2 * p][4 * tc + j]     = lo;   // row 4tr+2p
                s_lg[4 * tr + 2 * p + 1][4 * tc + j] = hi;   // row 4tr+2p+1
            }
        }
        // group 1 publishes its per-row ssq partials
        if (g == 1) {
            #pragma unroll
            for (int i = 0; i < 8; i++) {
                float s = ssq[i];
                #pragma unroll
                for (int o = 16; o; o >>= 1) s += __shfl_xor_sync(0xffffffffu, s, o);
                if (lane == 0) ssq2[w + 8 * i] = s;
            }
        }
        __syncthreads();

        if (g == 0) {
            float (*s_l1)[PAD] = (float (*)[PAD])(dsm + GRP_F);
            #pragma unroll
            for (int i = 0; i < 8; i++) {
                int rr = w + 8 * i;
                float s = ssq[i];
                #pragma unroll
                for (int o = 16; o; o >>= 1) s += __shfl_xor_sync(0xffffffffu, s, o);
                s += ssq2[rr];
                float r = rsqrtf(s * (1.0f / H) + 1e-6f);
                float v0 = r * (s_lg[rr][lane]      + s_l1[rr][lane]);
                float v1 = r * (s_lg[rr][lane + 32] + s_l1[rr][lane + 32]);
                float vals[4]; int ids[4];
                #pragma unroll
                for (int t4 = 0; t4 < 4; t4++) {
                    float cv; int ci;
                    if (v1 > v0) { cv = v1; ci = lane + 32; }
                    else         { cv = v0; ci = lane; }   // tie -> smaller index
                    #pragma unroll
                    for (int o = 16; o; o >>= 1) {
                        float ov = __shfl_xor_sync(0xffffffffu, cv, o);
                        int   oi = __shfl_xor_sync(0xffffffffu, ci, o);
                        if (ov > cv || (ov == cv && oi < ci)) { cv = ov; ci = oi; }
                    }
                    vals[t4] = cv; ids[t4] = ci;
                    if (ci < 32) { if (lane == ci)      v0 = -3.4e38f; }
                    else         { if (lane == ci - 32) v1 = -3.4e38f; }
                }
                if (lane == 0) {
                    int row = blockIdx.x * 64 + rr;
                    float mmax = vals[0];
                    float e0 = expf(vals[0] - mmax), e1 = expf(vals[1] - mmax);
                    float e2 = expf(vals[2] - mmax), e3 = expf(vals[3] - mmax);
                    float inv = 1.0f / (e0 + e1 + e2 + e3);
                    float* ow = out + OFF_W + (size_t)row * 4;
                    float* oi = out + OFF_I + (size_t)row * 4;
                    ow[0] = e0 * inv; ow[1] = e1 * inv; ow[2] = e2 * inv; ow[3] = e3 * inv;
                    oi[0] = (float)ids[0]; oi[1] = (float)ids[1];
                    oi[2] = (float)ids[2]; oi[3] = (float)ids[3];
                }
            }
        }
    } else {
        // ================= PREP (512 threads, 8 elems/thread) =================
        const int INF = 0x7fffffff;
        int b = blockIdx.x - GATE_BLOCKS;
        int t = tid;
        int base = t * 8;
        const int* pk = packed + b * S;
        const int* m  = mm + b * S;

        int p[8]; bool v[8];
        #pragma unroll
        for (int c = 0; c < 2; c++) {
            int4 pp4 = ((const int4*)(pk + base))[c];
            int4 mm4 = ((const int4*)(m + base))[c];
            p[4*c+0] = pp4.x; p[4*c+1] = pp4.y; p[4*c+2] = pp4.z; p[4*c+3] = pp4.w;
            v[4*c+0] = (mm4.x == 1) | (mm4.x == 2);
            v[4*c+1] = (mm4.y == 1) | (mm4.y == 2);
            v[4*c+2] = (mm4.z == 1) | (mm4.z == 2);
            v[4*c+3] = (mm4.w == 1) | (mm4.w == 2);
        }
        int  pprev = (base > 0) ? pk[base - 1] : -123456;
        int  pnext = (base + 8 < S) ? pk[base + 8] : -123456;
        int  mprev = (base > 0) ? m[base - 1] : 0;
        int  mnext = (base + 8 < S) ? m[base + 8] : 0;
        bool vprev = (mprev == 1) | (mprev == 2);
        bool vnext = (mnext == 1) | (mnext == 2);

        int dloc[8];
        {
            int run = -1, pp = pprev;
            #pragma unroll
            for (int j = 0; j < 8; j++) {
                if (p[j] != pp) run = base + j;
                dloc[j] = run; pp = p[j];
            }
            int ex = blk_excl_max512(run, t, sc);
            #pragma unroll
            for (int j = 0; j < 8; j++) if (ex > dloc[j]) dloc[j] = ex;
        }
        int vloc[8];
        {
            int run = -1; bool pv = vprev;
            #pragma unroll
            for (int j = 0; j < 8; j++) {
                if (v[j] && !pv) run = base + j;
                vloc[j] = run; pv = v[j];
            }
            int ex = blk_excl_max512(run, t, sc);
            #pragma unroll
            for (int j = 0; j < 8; j++) if (ex > vloc[j]) vloc[j] = ex;
        }
        int dend[8];
        {
            int run = INF, np = pnext;
            #pragma unroll
            for (int jj = 7; jj >= 0; jj--) {
                if (p[jj] != np) run = base + jj;
                dend[jj] = run; np = p[jj];
            }
            int ex = blk_excl_min_bwd512(run, t, sc);
            #pragma unroll
            for (int j = 0; j < 8; j++) if (ex < dend[j]) dend[j] = ex;
        }
        int vend[8];
        {
            int run = INF; bool nv = vnext;
            #pragma unroll
            for (int jj = 7; jj >= 0; jj--) {
                if (v[jj] && !nv) run = base + jj;
                vend[jj] = run; nv = v[jj];
            }
            int ex = blk_excl_min_bwd512(run, t, sc);
            #pragma unroll
            for (int j = 0; j < 8; j++) if (ex < vend[j]) vend[j] = ex;
        }

        #pragma unroll
        for (int j = 0; j < 8; j++) {
            int q = base + j;
            int4 mt;
            if (p[j] <= 0) {
                mt.x = S; mt.y = S; mt.z = S; mt.w = -1;
            } else {
                int flo = dloc[j];
                mt.x = flo;
                int s1 = q - (SW - 1);
                mt.y = (s1 > flo) ? s1 : flo;
                if (v[j]) {
                    int vl = vloc[j]; if (flo > vl) vl = flo;
                    int vh = vend[j]; if (dend[j] < vh) vh = dend[j];
                    mt.z = vl; mt.w = vh;
                } else {
                    mt.z = S; mt.w = -1;
                }
            }
            g_qmeta[b * S + q] = mt;
        }
    }
}

// ---------------------------------------------------------------------------
// K2: mask writer. 2048 blocks x 4 q-rows, interval predicates, plain stores.
// ---------------------------------------------------------------------------
__global__ __launch_bounds__(256) void mask_kernel(float* __restrict__ out) {
    int mb = blockIdx.x;                    // 0 .. 2047
    int b  = mb >> 10;
    int q0 = (mb & 1023) << 2;
    int tid = threadIdx.x;

    float* fullb = out + (size_t)b * S * S;
    float* slidb = out + OFF_SLID + (size_t)b * S * S;

    #pragma unroll
    for (int qi = 0; qi < 4; qi++) {
        int q = q0 + qi;
        int4 mt = g_qmeta[b * S + q];       // {flo, s1lo, v2lo, v2hi}
        int flo = mt.x, slo = mt.y, vlo = mt.z;
        unsigned vspan = (unsigned)(mt.w - mt.z);
        float4* fo = (float4*)(fullb + (size_t)q * S);
        float4* so = (float4*)(slidb + (size_t)q * S);
        #pragma unroll
        for (int it = 0; it < 4; it++) {
            int k4 = tid + it * 256;
            int kv = k4 * 4;
            float4 f, sl;
            #pragma unroll
            for (int j = 0; j < 4; j++) {
                int k = kv + j;
                bool fb = (k >= flo) & (k <= q);
                bool sb = ((k >= slo) & (k <= q)) | ((unsigned)(k - vlo) <= vspan);
                (&f.x)[j]  = fb ? 0.0f : NEGF;
                (&sl.x)[j] = sb ? 0.0f : NEGF;
            }
            fo[k4] = f;
            so[k4] = sl;
        }
    }
}

// ---------------------------------------------------------------------------
extern "C" void kernel_launch(void* const* d_in, const int* in_sizes, int n_in,
                              void* d_out, int out_size) {
    const float* x      = (const float*)d_in[0];
    const int*   packed = (const int*)d_in[1];
    const int*   mm     = (const int*)d_in[2];
    const float* scale  = (const float*)d_in[3];
    const float* pw     = (const float*)d_in[4];
    float* out = (float*)d_out;

    static int smem_set = 0;
    if (!smem_set) {
        cudaFuncSetAttribute(gate_prep_kernel,
                             cudaFuncAttributeMaxDynamicSharedMemorySize,
                             GATE_SMEM_BYTES);
        smem_set = 1;
    }

    fold_kernel<<<128, 256>>>(scale, pw);
    gate_prep_kernel<<<GATE_BLOCKS + B, 512, GATE_SMEM_BYTES>>>(x, packed, mm, out);
    mask_kernel<<<2048, 256>>>(out);
}

// round 15
// speedup vs baseline: 1.3454x; 1.3454x over previous
#include <cuda_runtime.h>
#include <math.h>
#include <stdint.h>

#define H 2048
#define E 64
#define S 4096
#define B 2
#define SW 1024
#define NEGF (-3.4028234663852886e38f)   // -FLT_MAX == finfo(float32).min

#define OFF_SLID 33554432ull             // 2*4096*4096
#define OFF_W    67108864ull
#define OFF_I    67141632ull             // OFF_W + 8192*4

#define RSQRT_H 0.022097086912079608f    // 1/sqrt(2048)
#define FOLD_BLOCKS 128
#define GATE_BLOCKS 128                  // 64 rows per block
#define NC (H / 16)                      // 128 k16-chunks

// gate epilogue dynamic smem: sml[4][64][68] + ssqs[4][64]
#define SML_F (4 * 64 * 68)
#define GATE_SMEM_BYTES ((SML_F + 4 * 64) * 4)

// scratch (no allocations allowed)
__device__ int4 g_qmeta[B * S];                         // {flo, s1lo, v2lo, v2hi}
__device__ __align__(16) unsigned g_wfmt1[NC * 8 * 32 * 4];  // {hi0,hi1,mid0,mid1}
__device__ __align__(16) unsigned g_wfmt2[NC * 8 * 32 * 2];  // {lo0,lo1}

// ---------------------------------------------------------------------------
// exact 3-way bf16 split of an fp32 pair (hi/mid/lo reconstruct exactly)
// ---------------------------------------------------------------------------
__device__ __forceinline__ void split_pair(float a, float b, unsigned& hi,
                                           unsigned& mid, unsigned& lo) {
    hi = __byte_perm(__float_as_uint(a), __float_as_uint(b), 0x7632);
    float ha = __uint_as_float(__float_as_uint(a) & 0xFFFF0000u);
    float hb = __uint_as_float(__float_as_uint(b) & 0xFFFF0000u);
    float ra = a - ha, rb = b - hb;
    mid = __byte_perm(__float_as_uint(ra), __float_as_uint(rb), 0x7632);
    float ma = __uint_as_float(__float_as_uint(ra) & 0xFFFF0000u);
    float mb = __uint_as_float(__float_as_uint(rb) & 0xFFFF0000u);
    float la = ra - ma, lb = rb - mb;          // exactly bf16-representable
    lo = __byte_perm(__float_as_uint(la), __float_as_uint(lb), 0x7632);
}

__device__ __forceinline__ void mma16816(float* c, const unsigned* a,
                                         unsigned b0, unsigned b1) {
    asm("mma.sync.aligned.m16n8k16.row.col.f32.bf16.bf16.f32 "
        "{%0,%1,%2,%3}, {%4,%5,%6,%7}, {%8,%9}, {%0,%1,%2,%3};"
        : "+f"(c[0]), "+f"(c[1]), "+f"(c[2]), "+f"(c[3])
        : "r"(a[0]), "r"(a[1]), "r"(a[2]), "r"(a[3]), "r"(b0), "r"(b1));
}

// ---------------------------------------------------------------------------
// block scans for prep (256 threads)
// ---------------------------------------------------------------------------
__device__ __forceinline__ int blk_excl_max(int agg, int t, int* sc) {
    int lane = t & 31, w = t >> 5;
    int inc = agg;
    #pragma unroll
    for (int o = 1; o < 32; o <<= 1) {
        int u = __shfl_up_sync(0xffffffffu, inc, o);
        if (lane >= o) inc = max(inc, u);
    }
    if (lane == 31) sc[w] = inc;
    __syncthreads();
    int wex = -0x7fffffff;
    for (int i = 0; i < w; i++) wex = max(wex, sc[i]);
    int lex = __shfl_up_sync(0xffffffffu, inc, 1);
    if (lane == 0) lex = -0x7fffffff;
    __syncthreads();
    return max(wex, lex);
}
__device__ __forceinline__ int blk_excl_min_bwd(int agg, int t, int* sc) {
    int lane = t & 31, w = t >> 5;
    int inc = agg;
    #pragma unroll
    for (int o = 1; o < 32; o <<= 1) {
        int u = __shfl_down_sync(0xffffffffu, inc, o);
        if (lane < 32 - o) inc = min(inc, u);
    }
    if (lane == 0) sc[w] = inc;
    __syncthreads();
    int wex = 0x7fffffff;
    for (int i = w + 1; i < 8; i++) wex = min(wex, sc[i]);
    int lex = __shfl_down_sync(0xffffffffu, inc, 1);
    if (lane == 31) lex = 0x7fffffff;
    __syncthreads();
    return min(wex, lex);
}

// ---------------------------------------------------------------------------
// K0: fold W (scale, H^-0.5) -> 3-way bf16 split, B-fragment register images
//     (+ 2 prep blocks for mask metadata)
// B frag (m16n8k16, col): thread t (g=t>>2 = n, tg=t&3):
//   reg0 = {B[2tg][g], B[2tg+1][g]}, reg1 = {B[2tg+8][g], B[2tg+9][g]}
//   with B[k][n] = Wsc[e = nt*8+g][c*16 + k]
// ---------------------------------------------------------------------------
__global__ __launch_bounds__(256) void foldprep_kernel(const float* __restrict__ scale,
                                                       const float* __restrict__ pw,
                                                       const int* __restrict__ packed,
                                                       const int* __restrict__ mm) {
    if (blockIdx.x < FOLD_BLOCKS) {
        int i = blockIdx.x * 1024 + threadIdx.x * 4;     // over E*H = 131072
        float4 pw4 = *(const float4*)(pw + i);
        float4 sc4 = *(const float4*)(scale + (i & (H - 1)));
        float v[4] = { pw4.x * sc4.x * RSQRT_H, pw4.y * sc4.y * RSQRT_H,
                       pw4.z * sc4.z * RSQRT_H, pw4.w * sc4.w * RSQRT_H };
        int e  = i >> 11;
        int h  = i & (H - 1);
        int c  = h >> 4, kk = h & 15;                    // kk % 4 == 0
        int nt = e >> 3, g = e & 7;
        #pragma unroll
        for (int j = 0; j < 2; j++) {
            unsigned hi, mid, lo;
            split_pair(v[2 * j], v[2 * j + 1], hi, mid, lo);
            int kkj = kk + 2 * j;
            int R = kkj >> 3;
            int tg = (kkj & 7) >> 1;
            int t = g * 4 + tg;
            size_t b1 = ((size_t)(c * 8 + nt) * 32 + t) * 4;
            g_wfmt1[b1 + R]     = hi;
            g_wfmt1[b1 + 2 + R] = mid;
            g_wfmt2[((size_t)(c * 8 + nt) * 32 + t) * 2 + R] = lo;
        }
    } else {
        // ================= PREP =================
        __shared__ int sc[8];
        const int INF = 0x7fffffff;
        int b = blockIdx.x - FOLD_BLOCKS;
        int t = threadIdx.x;
        int base = t * 16;
        const int* pk = packed + b * S;
        const int* m  = mm + b * S;

        int p[16]; bool v[16];
        #pragma unroll
        for (int c4 = 0; c4 < 4; c4++) {
            int4 pp4 = ((const int4*)(pk + base))[c4];
            int4 mm4 = ((const int4*)(m + base))[c4];
            p[4*c4+0] = pp4.x; p[4*c4+1] = pp4.y; p[4*c4+2] = pp4.z; p[4*c4+3] = pp4.w;
            v[4*c4+0] = (mm4.x == 1) | (mm4.x == 2);
            v[4*c4+1] = (mm4.y == 1) | (mm4.y == 2);
            v[4*c4+2] = (mm4.z == 1) | (mm4.z == 2);
            v[4*c4+3] = (mm4.w == 1) | (mm4.w == 2);
        }
        int  pprev = (base > 0) ? pk[base - 1] : -123456;
        int  pnext = (base + 16 < S) ? pk[base + 16] : -123456;
        int  mprev = (base > 0) ? m[base - 1] : 0;
        int  mnext = (base + 16 < S) ? m[base + 16] : 0;
        bool vprev = (mprev == 1) | (mprev == 2);
        bool vnext = (mnext == 1) | (mnext == 2);

        int dloc[16];
        {
            int run = -1, pp = pprev;
            #pragma unroll
            for (int j = 0; j < 16; j++) {
                if (p[j] != pp) run = base + j;
                dloc[j] = run; pp = p[j];
            }
            int ex = blk_excl_max(run, t, sc);
            #pragma unroll
            for (int j = 0; j < 16; j++) if (ex > dloc[j]) dloc[j] = ex;
        }
        int vloc[16];
        {
            int run = -1; bool pv = vprev;
            #pragma unroll
            for (int j = 0; j < 16; j++) {
                if (v[j] && !pv) run = base + j;
                vloc[j] = run; pv = v[j];
            }
            int ex = blk_excl_max(run, t, sc);
            #pragma unroll
            for (int j = 0; j < 16; j++) if (ex > vloc[j]) vloc[j] = ex;
        }
        int dend[16];
        {
            int run = INF, np = pnext;
            #pragma unroll
            for (int jj = 15; jj >= 0; jj--) {
                if (p[jj] != np) run = base + jj;
                dend[jj] = run; np = p[jj];
            }
            int ex = blk_excl_min_bwd(run, t, sc);
            #pragma unroll
            for (int j = 0; j < 16; j++) if (ex < dend[j]) dend[j] = ex;
        }
        int vend[16];
        {
            int run = INF; bool nv = vnext;
            #pragma unroll
            for (int jj = 15; jj >= 0; jj--) {
                if (v[jj] && !nv) run = base + jj;
                vend[jj] = run; nv = v[jj];
            }
            int ex = blk_excl_min_bwd(run, t, sc);
            #pragma unroll
            for (int j = 0; j < 16; j++) if (ex < vend[j]) vend[j] = ex;
        }

        #pragma unroll
        for (int j = 0; j < 16; j++) {
            int q = base + j;
            int4 mt;
            if (p[j] <= 0) {
                mt.x = S; mt.y = S; mt.z = S; mt.w = -1;
            } else {
                int flo = dloc[j];
                mt.x = flo;
                int s1 = q - (SW - 1);
                mt.y = (s1 > flo) ? s1 : flo;
                if (v[j]) {
                    int vl = vloc[j]; if (flo > vl) vl = flo;
                    int vh = vend[j]; if (dend[j] < vh) vh = dend[j];
                    mt.z = vl; mt.w = vh;
                } else {
                    mt.z = S; mt.w = -1;
                }
            }
            g_qmeta[b * S + q] = mt;
        }
    }
}

// ---------------------------------------------------------------------------
// K1: mma.sync gate. 128 blocks x 256 thr. Warp w: rowset s=w>>2 (32 rows),
// K quarter q=w&3 (32 k16-chunks). Per warp: 2 m16 tiles x 8 n8 tiles,
// 6 split-product MMAs each. Epilogue: no-atomic smem reduce + rms + top-4.
// ---------------------------------------------------------------------------
__global__ __launch_bounds__(256) void gate_mma_kernel(const float* __restrict__ x,
                                                       float* __restrict__ out) {
    extern __shared__ float dsm[];
    float (*sml)[64][68] = (float (*)[64][68])dsm;        // [q][row][expert]
    float (*ssqs)[64]    = (float (*)[64])(dsm + SML_F);  // [q][row]

    int tid = threadIdx.x;
    int w = tid >> 5, lane = tid & 31;
    int s = w >> 2, q = w & 3;
    int g = lane >> 2, tg = lane & 3;
    const float* xb = x + (size_t)blockIdx.x * 64 * H;
    int rowb = s * 32;

    float acc[2][8][4] = {};
    float ssq4[4] = {};          // [mt*2 + (0: row g, 1: row g+8)]

    for (int step = 0; step < 32; step++) {
        int c = q * 32 + step;
        int col = c * 16 + 2 * tg;
        unsigned Ah[2][4], Am[2][4], Al[2][4];
        #pragma unroll
        for (int mt = 0; mt < 2; mt++) {
            const float* r0p = xb + (size_t)(rowb + mt * 16 + g) * H + col;
            const float* r1p = r0p + 8 * H;
            float2 p00 = *(const float2*)r0p;
            float2 p01 = *(const float2*)(r0p + 8);
            float2 p10 = *(const float2*)r1p;
            float2 p11 = *(const float2*)(r1p + 8);
            ssq4[mt*2+0] = fmaf(p00.x, p00.x, fmaf(p00.y, p00.y,
                            fmaf(p01.x, p01.x, fmaf(p01.y, p01.y, ssq4[mt*2+0]))));
            ssq4[mt*2+1] = fmaf(p10.x, p10.x, fmaf(p10.y, p10.y,
                            fmaf(p11.x, p11.x, fmaf(p11.y, p11.y, ssq4[mt*2+1]))));
            split_pair(p00.x, p00.y, Ah[mt][0], Am[mt][0], Al[mt][0]);
            split_pair(p10.x, p10.y, Ah[mt][1], Am[mt][1], Al[mt][1]);
            split_pair(p01.x, p01.y, Ah[mt][2], Am[mt][2], Al[mt][2]);
            split_pair(p11.x, p11.y, Ah[mt][3], Am[mt][3], Al[mt][3]);
        }
        #pragma unroll
        for (int nt = 0; nt < 8; nt++) {
            uint4 bA = *((const uint4*)g_wfmt1 + ((c * 8 + nt) * 32 + lane));
            uint2 bL = *((const uint2*)g_wfmt2 + ((c * 8 + nt) * 32 + lane));
            #pragma unroll
            for (int mt = 0; mt < 2; mt++) {
                mma16816(acc[mt][nt], Ah[mt], bA.x, bA.y);   // hi * hi
                mma16816(acc[mt][nt], Ah[mt], bA.z, bA.w);   // hi * mid
                mma16816(acc[mt][nt], Am[mt], bA.x, bA.y);   // mid * hi
                mma16816(acc[mt][nt], Am[mt], bA.z, bA.w);   // mid * mid
                mma16816(acc[mt][nt], Ah[mt], bL.x, bL.y);   // hi * lo
                mma16816(acc[mt][nt], Al[mt], bA.x, bA.y);   // lo * hi
            }
        }
    }

    // partial logits -> sml[q] (every slot written exactly once: no atomics)
    #pragma unroll
    for (int mt = 0; mt < 2; mt++) {
        int rl = rowb + mt * 16 + g;
        #pragma unroll
        for (int nt = 0; nt < 8; nt++) {
            int e0 = nt * 8 + 2 * tg;
            *(float2*)&sml[q][rl][e0]     = make_float2(acc[mt][nt][0], acc[mt][nt][1]);
            *(float2*)&sml[q][rl + 8][e0] = make_float2(acc[mt][nt][2], acc[mt][nt][3]);
        }
    }
    // ssq partials: quad-reduce over tg, lane tg==0 writes
    #pragma unroll
    for (int i = 0; i < 4; i++) {
        float v = ssq4[i];
        v += __shfl_xor_sync(0xffffffffu, v, 1);
        v += __shfl_xor_sync(0xffffffffu, v, 2);
        if (tg == 0) ssqs[q][rowb + (i >> 1) * 16 + g + (i & 1) * 8] = v;
    }
    __syncthreads();

    // top-4 + renormalized softmax: warp w handles rows 8w..8w+7
    #pragma unroll
    for (int i = 0; i < 8; i++) {
        int rr = w * 8 + i;
        float ssq = ssqs[0][rr] + ssqs[1][rr] + ssqs[2][rr] + ssqs[3][rr];
        float r = rsqrtf(ssq * (1.0f / H) + 1e-6f);
        float v0 = r * (sml[0][rr][lane] + sml[1][rr][lane]
                      + sml[2][rr][lane] + sml[3][rr][lane]);
        float v1 = r * (sml[0][rr][lane + 32] + sml[1][rr][lane + 32]
                      + sml[2][rr][lane + 32] + sml[3][rr][lane + 32]);
        float vals[4]; int ids[4];
        #pragma unroll
        for (int t4 = 0; t4 < 4; t4++) {
            float cv; int ci;
            if (v1 > v0) { cv = v1; ci = lane + 32; }
            else         { cv = v0; ci = lane; }   // tie -> smaller index
            #pragma unroll
            for (int o = 16; o; o >>= 1) {
                float ov = __shfl_xor_sync(0xffffffffu, cv, o);
                int   oi = __shfl_xor_sync(0xffffffffu, ci, o);
                if (ov > cv || (ov == cv && oi < ci)) { cv = ov; ci = oi; }
            }
            vals[t4] = cv; ids[t4] = ci;
            if (ci < 32) { if (lane == ci)      v0 = -3.4e38f; }
            else         { if (lane == ci - 32) v1 = -3.4e38f; }
        }
        if (lane == 0) {
            int row = blockIdx.x * 64 + rr;
            float mmax = vals[0];
            float e0 = expf(vals[0] - mmax), e1 = expf(vals[1] - mmax);
            float e2 = expf(vals[2] - mmax), e3 = expf(vals[3] - mmax);
            float inv = 1.0f / (e0 + e1 + e2 + e3);
            float* ow = out + OFF_W + (size_t)row * 4;
            float* oi = out + OFF_I + (size_t)row * 4;
            ow[0] = e0 * inv; ow[1] = e1 * inv; ow[2] = e2 * inv; ow[3] = e3 * inv;
            oi[0] = (float)ids[0]; oi[1] = (float)ids[1];
            oi[2] = (float)ids[2]; oi[3] = (float)ids[3];
        }
    }
}

// ---------------------------------------------------------------------------
// K2: mask writer. 2048 blocks x 4 q-rows, interval predicates, plain stores.
// ---------------------------------------------------------------------------
__global__ __launch_bounds__(256) void mask_kernel(float* __restrict__ out) {
    int mb = blockIdx.x;                    // 0 .. 2047
    int b  = mb >> 10;
    int q0 = (mb & 1023) << 2;
    int tid = threadIdx.x;

    float* fullb = out + (size_t)b * S * S;
    float* slidb = out + OFF_SLID + (size_t)b * S * S;

    #pragma unroll
    for (int qi = 0; qi < 4; qi++) {
        int q = q0 + qi;
        int4 mt = g_qmeta[b * S + q];       // {flo, s1lo, v2lo, v2hi}
        int flo = mt.x, slo = mt.y, vlo = mt.z;
        unsigned vspan = (unsigned)(mt.w - mt.z);
        float4* fo = (float4*)(fullb + (size_t)q * S);
        float4* so = (float4*)(slidb + (size_t)q * S);
        #pragma unroll
        for (int it = 0; it < 4; it++) {
            int k4 = tid + it * 256;
            int kv = k4 * 4;
            float4 f, sl;
            #pragma unroll
            for (int j = 0; j < 4; j++) {
                int k = kv + j;
                bool fb = (k >= flo) & (k <= q);
                bool sb = ((k >= slo) & (k <= q)) | ((unsigned)(k - vlo) <= vspan);
                (&f.x)[j]  = fb ? 0.0f : NEGF;
                (&sl.x)[j] = sb ? 0.0f : NEGF;
            }
            fo[k4] = f;
            so[k4] = sl;
        }
    }
}

// ---------------------------------------------------------------------------
extern "C" void kernel_launch(void* const* d_in, const int* in_sizes, int n_in,
                              void* d_out, int out_size) {
    const float* x      = (const float*)d_in[0];
    const int*   packed = (const int*)d_in[1];
    const int*   mm     = (const int*)d_in[2];
    const float* scale  = (const float*)d_in[3];
    const float* pw     = (const float*)d_in[4];
    float* out = (float*)d_out;

    static int smem_set = 0;
    if (!smem_set) {
        cudaFuncSetAttribute(gate_mma_kernel,
                             cudaFuncAttributeMaxDynamicSharedMemorySize,
                             GATE_SMEM_BYTES);
        smem_set = 1;
    }

    foldprep_kernel<<<FOLD_BLOCKS + B, 256>>>(scale, pw, packed, mm);
    gate_mma_kernel<<<GATE_BLOCKS, 256, GATE_SMEM_BYTES>>>(x, out);
    mask_kernel<<<2048, 256>>>(out);
}

// round 16
// speedup vs baseline: 1.8393x; 1.3672x over previous
#include <cuda_runtime.h>
#include <cuda_fp16.h>
#include <math.h>
#include <stdint.h>

#define H 2048
#define E 64
#define S 4096
#define B 2
#define SW 1024
#define NEGF (-3.4028234663852886e38f)   // -FLT_MAX == finfo(float32).min

#define OFF_SLID 33554432ull             // 2*4096*4096
#define OFF_W    67108864ull
#define OFF_I    67141632ull             // OFF_W + 8192*4

#define RSQRT_H 0.022097086912079608f    // 1/sqrt(2048)
#define FOLD_BLOCKS 128
#define GATE_BLOCKS 128                  // 64 rows per block
#define NC (H / 16)                      // 128 k16-chunks

// gate epilogue dynamic smem: sml[4][64][68] + ssqs[4][64]
#define SML_F (4 * 64 * 68)
#define GATE_SMEM_BYTES ((SML_F + 4 * 64) * 4)

// scale both operands by 256 (keeps fp16 "mid" splits in normal range);
// compensate exactly with 2^-16 folded into the rmsnorm multiplier.
#define OPSCALE 256.0f
#define INV_SCALE2 (1.0f / 65536.0f)

// scratch (no allocations allowed)
__device__ int4 g_qmeta[B * S];                         // {flo, s1lo, v2lo, v2hi}
__device__ __align__(16) unsigned g_wfmt[NC * 8 * 32 * 4];  // {wh0,wh1,wm0,wm1}

// ---------------------------------------------------------------------------
// fp16 2-way split of a (pre-scaled) fp32 pair: f = hi + mid + O(2^-22 f)
// ---------------------------------------------------------------------------
__device__ __forceinline__ void split_f16(float a, float b, unsigned& hi,
                                          unsigned& mid) {
    __half2 h = __float22half2_rn(make_float2(a, b));
    float2 hb = __half22float2(h);
    __half2 m = __float22half2_rn(make_float2(a - hb.x, b - hb.y));
    hi  = *(unsigned*)&h;
    mid = *(unsigned*)&m;
}

__device__ __forceinline__ void mma16816(float* c, const unsigned* a,
                                         unsigned b0, unsigned b1) {
    asm("mma.sync.aligned.m16n8k16.row.col.f32.f16.f16.f32 "
        "{%0,%1,%2,%3}, {%4,%5,%6,%7}, {%8,%9}, {%0,%1,%2,%3};"
        : "+f"(c[0]), "+f"(c[1]), "+f"(c[2]), "+f"(c[3])
        : "r"(a[0]), "r"(a[1]), "r"(a[2]), "r"(a[3]), "r"(b0), "r"(b1));
}

// ---------------------------------------------------------------------------
// block scans for prep (256 threads)
// ---------------------------------------------------------------------------
__device__ __forceinline__ int blk_excl_max(int agg, int t, int* sc) {
    int lane = t & 31, w = t >> 5;
    int inc = agg;
    #pragma unroll
    for (int o = 1; o < 32; o <<= 1) {
        int u = __shfl_up_sync(0xffffffffu, inc, o);
        if (lane >= o) inc = max(inc, u);
    }
    if (lane == 31) sc[w] = inc;
    __syncthreads();
    int wex = -0x7fffffff;
    for (int i = 0; i < w; i++) wex = max(wex, sc[i]);
    int lex = __shfl_up_sync(0xffffffffu, inc, 1);
    if (lane == 0) lex = -0x7fffffff;
    __syncthreads();
    return max(wex, lex);
}
__device__ __forceinline__ int blk_excl_min_bwd(int agg, int t, int* sc) {
    int lane = t & 31, w = t >> 5;
    int inc = agg;
    #pragma unroll
    for (int o = 1; o < 32; o <<= 1) {
        int u = __shfl_down_sync(0xffffffffu, inc, o);
        if (lane < 32 - o) inc = min(inc, u);
    }
    if (lane == 0) sc[w] = inc;
    __syncthreads();
    int wex = 0x7fffffff;
    for (int i = w + 1; i < 8; i++) wex = min(wex, sc[i]);
    int lex = __shfl_down_sync(0xffffffffu, inc, 1);
    if (lane == 31) lex = 0x7fffffff;
    __syncthreads();
    return min(wex, lex);
}

// ---------------------------------------------------------------------------
// K0: fold W (scale, H^-0.5, x256) -> fp16 2-way split B-fragment images
//     (+ 2 prep blocks for mask metadata)
// B frag (m16n8k16, col): thread t (g=t>>2 = n, tg=t&3):
//   reg0 = {B[2tg][g], B[2tg+1][g]}, reg1 = {B[2tg+8][g], B[2tg+9][g]}
// ---------------------------------------------------------------------------
__global__ __launch_bounds__(256) void foldprep_kernel(const float* __restrict__ scale,
                                                       const float* __restrict__ pw,
                                                       const int* __restrict__ packed,
                                                       const int* __restrict__ mm) {
    if (blockIdx.x < FOLD_BLOCKS) {
        int i = blockIdx.x * 1024 + threadIdx.x * 4;     // over E*H = 131072
        float4 pw4 = *(const float4*)(pw + i);
        float4 sc4 = *(const float4*)(scale + (i & (H - 1)));
        const float K = RSQRT_H * OPSCALE;
        float v[4] = { pw4.x * sc4.x * K, pw4.y * sc4.y * K,
                       pw4.z * sc4.z * K, pw4.w * sc4.w * K };
        int e  = i >> 11;
        int h  = i & (H - 1);
        int c  = h >> 4, kk = h & 15;                    // kk % 4 == 0
        int nt = e >> 3, g = e & 7;
        #pragma unroll
        for (int j = 0; j < 2; j++) {
            unsigned hi, mid;
            split_f16(v[2 * j], v[2 * j + 1], hi, mid);
            int kkj = kk + 2 * j;
            int R = kkj >> 3;
            int tg = (kkj & 7) >> 1;
            int t = g * 4 + tg;
            size_t b1 = ((size_t)(c * 8 + nt) * 32 + t) * 4;
            g_wfmt[b1 + R]     = hi;
            g_wfmt[b1 + 2 + R] = mid;
        }
    } else {
        // ================= PREP =================
        __shared__ int sc[8];
        const int INF = 0x7fffffff;
        int b = blockIdx.x - FOLD_BLOCKS;
        int t = threadIdx.x;
        int base = t * 16;
        const int* pk = packed + b * S;
        const int* m  = mm + b * S;

        int p[16]; bool v[16];
        #pragma unroll
        for (int c4 = 0; c4 < 4; c4++) {
            int4 pp4 = ((const int4*)(pk + base))[c4];
            int4 mm4 = ((const int4*)(m + base))[c4];
            p[4*c4+0] = pp4.x; p[4*c4+1] = pp4.y; p[4*c4+2] = pp4.z; p[4*c4+3] = pp4.w;
            v[4*c4+0] = (mm4.x == 1) | (mm4.x == 2);
            v[4*c4+1] = (mm4.y == 1) | (mm4.y == 2);
            v[4*c4+2] = (mm4.z == 1) | (mm4.z == 2);
            v[4*c4+3] = (mm4.w == 1) | (mm4.w == 2);
        }
        int  pprev = (base > 0) ? pk[base - 1] : -123456;
        int  pnext = (base + 16 < S) ? pk[base + 16] : -123456;
        int  mprev = (base > 0) ? m[base - 1] : 0;
        int  mnext = (base + 16 < S) ? m[base + 16] : 0;
        bool vprev = (mprev == 1) | (mprev == 2);
        bool vnext = (mnext == 1) | (mnext == 2);

        int dloc[16];
        {
            int run = -1, pp = pprev;
            #pragma unroll
            for (int j = 0; j < 16; j++) {
                if (p[j] != pp) run = base + j;
                dloc[j] = run; pp = p[j];
            }
            int ex = blk_excl_max(run, t, sc);
            #pragma unroll
            for (int j = 0; j < 16; j++) if (ex > dloc[j]) dloc[j] = ex;
        }
        int vloc[16];
        {
            int run = -1; bool pv = vprev;
            #pragma unroll
            for (int j = 0; j < 16; j++) {
                if (v[j] && !pv) run = base + j;
                vloc[j] = run; pv = v[j];
            }
            int ex = blk_excl_max(run, t, sc);
            #pragma unroll
            for (int j = 0; j < 16; j++) if (ex > vloc[j]) vloc[j] = ex;
        }
        int dend[16];
        {
            int run = INF, np = pnext;
            #pragma unroll
            for (int jj = 15; jj >= 0; jj--) {
                if (p[jj] != np) run = base + jj;
                dend[jj] = run; np = p[jj];
            }
            int ex = blk_excl_min_bwd(run, t, sc);
            #pragma unroll
            for (int j = 0; j < 16; j++) if (ex < dend[j]) dend[j] = ex;
        }
        int vend[16];
        {
            int run = INF; bool nv = vnext;
            #pragma unroll
            for (int jj = 15; jj >= 0; jj--) {
                if (v[jj] && !nv) run = base + jj;
                vend[jj] = run; nv = v[jj];
            }
            int ex = blk_excl_min_bwd(run, t, sc);
            #pragma unroll
            for (int j = 0; j < 16; j++) if (ex < vend[j]) vend[j] = ex;
        }

        #pragma unroll
        for (int j = 0; j < 16; j++) {
            int q = base + j;
            int4 mt;
            if (p[j] <= 0) {
                mt.x = S; mt.y = S; mt.z = S; mt.w = -1;
            } else {
                int flo = dloc[j];
                mt.x = flo;
                int s1 = q - (SW - 1);
                mt.y = (s1 > flo) ? s1 : flo;
                if (v[j]) {
                    int vl = vloc[j]; if (flo > vl) vl = flo;
                    int vh = vend[j]; if (dend[j] < vh) vh = dend[j];
                    mt.z = vl; mt.w = vh;
                } else {
                    mt.z = S; mt.w = -1;
                }
            }
            g_qmeta[b * S + q] = mt;
        }
    }
}

// ---------------------------------------------------------------------------
// K1: mma.sync gate (fp16 2-split, 3 products). 128 blocks x 256 thr.
// Warp w: rowset s=w>>2 (32 rows), K quarter q=w&3. Per warp per step:
// 2 m16 x 8 n8 tiles x 3 MMAs. Epilogue: smem reduce + rms + top-4.
// ---------------------------------------------------------------------------
__global__ __launch_bounds__(256) void gate_mma_kernel(const float* __restrict__ x,
                                                       float* __restrict__ out) {
    extern __shared__ float dsm[];
    float (*sml)[64][68] = (float (*)[64][68])dsm;        // [q][row][expert]
    float (*ssqs)[64]    = (float (*)[64])(dsm + SML_F);  // [q][row]

    int tid = threadIdx.x;
    int w = tid >> 5, lane = tid & 31;
    int s = w >> 2, q = w & 3;
    int g = lane >> 2, tg = lane & 3;
    const float* xb = x + (size_t)blockIdx.x * 64 * H;
    int rowb = s * 32;

    float acc[2][8][4] = {};
    float ssq4[4] = {};          // [mt*2 + (0: row g, 1: row g+8)]

    for (int step = 0; step < 32; step++) {
        int c = q * 32 + step;
        int col = c * 16 + 2 * tg;
        unsigned Ah[2][4], Am[2][4];
        #pragma unroll
        for (int mt = 0; mt < 2; mt++) {
            const float* r0p = xb + (size_t)(rowb + mt * 16 + g) * H + col;
            const float* r1p = r0p + 8 * H;
            float2 p00 = *(const float2*)r0p;
            float2 p01 = *(const float2*)(r0p + 8);
            float2 p10 = *(const float2*)r1p;
            float2 p11 = *(const float2*)(r1p + 8);
            ssq4[mt*2+0] = fmaf(p00.x, p00.x, fmaf(p00.y, p00.y,
                            fmaf(p01.x, p01.x, fmaf(p01.y, p01.y, ssq4[mt*2+0]))));
            ssq4[mt*2+1] = fmaf(p10.x, p10.x, fmaf(p10.y, p10.y,
                            fmaf(p11.x, p11.x, fmaf(p11.y, p11.y, ssq4[mt*2+1]))));
            split_f16(p00.x * OPSCALE, p00.y * OPSCALE, Ah[mt][0], Am[mt][0]);
            split_f16(p10.x * OPSCALE, p10.y * OPSCALE, Ah[mt][1], Am[mt][1]);
            split_f16(p01.x * OPSCALE, p01.y * OPSCALE, Ah[mt][2], Am[mt][2]);
            split_f16(p11.x * OPSCALE, p11.y * OPSCALE, Ah[mt][3], Am[mt][3]);
        }
        #pragma unroll
        for (int nt = 0; nt < 8; nt++) {
            uint4 bA = *((const uint4*)g_wfmt + ((c * 8 + nt) * 32 + lane));
            #pragma unroll
            for (int mt = 0; mt < 2; mt++) {
                mma16816(acc[mt][nt], Ah[mt], bA.x, bA.y);   // hi * hi
                mma16816(acc[mt][nt], Ah[mt], bA.z, bA.w);   // hi * mid
                mma16816(acc[mt][nt], Am[mt], bA.x, bA.y);   // mid * hi
            }
        }
    }

    // partial logits -> sml[q] (every slot written exactly once: no atomics)
    #pragma unroll
    for (int mt = 0; mt < 2; mt++) {
        int rl = rowb + mt * 16 + g;
        #pragma unroll
        for (int nt = 0; nt < 8; nt++) {
            int e0 = nt * 8 + 2 * tg;
            *(float2*)&sml[q][rl][e0]     = make_float2(acc[mt][nt][0], acc[mt][nt][1]);
            *(float2*)&sml[q][rl + 8][e0] = make_float2(acc[mt][nt][2], acc[mt][nt][3]);
        }
    }
    // ssq partials: quad-reduce over tg, lane tg==0 writes
    #pragma unroll
    for (int i = 0; i < 4; i++) {
        float v = ssq4[i];
        v += __shfl_xor_sync(0xffffffffu, v, 1);
        v += __shfl_xor_sync(0xffffffffu, v, 2);
        if (tg == 0) ssqs[q][rowb + (i >> 1) * 16 + g + (i & 1) * 8] = v;
    }
    __syncthreads();

    // top-4 + renormalized softmax: warp w handles rows 8w..8w+7
    #pragma unroll
    for (int i = 0; i < 8; i++) {
        int rr = w * 8 + i;
        float ssq = ssqs[0][rr] + ssqs[1][rr] + ssqs[2][rr] + ssqs[3][rr];
        float r = rsqrtf(ssq * (1.0f / H) + 1e-6f) * INV_SCALE2;
        float v0 = r * (sml[0][rr][lane] + sml[1][rr][lane]
                      + sml[2][rr][lane] + sml[3][rr][lane]);
        float v1 = r * (sml[0][rr][lane + 32] + sml[1][rr][lane + 32]
                      + sml[2][rr][lane + 32] + sml[3][rr][lane + 32]);
        float vals[4]; int ids[4];
        #pragma unroll
        for (int t4 = 0; t4 < 4; t4++) {
            float cv; int ci;
            if (v1 > v0) { cv = v1; ci = lane + 32; }
            else         { cv = v0; ci = lane; }   // tie -> smaller index
            #pragma unroll
            for (int o = 16; o; o >>= 1) {
                float ov = __shfl_xor_sync(0xffffffffu, cv, o);
                int   oi = __shfl_xor_sync(0xffffffffu, ci, o);
                if (ov > cv || (ov == cv && oi < ci)) { cv = ov; ci = oi; }
            }
            vals[t4] = cv; ids[t4] = ci;
            if (ci < 32) { if (lane == ci)      v0 = -3.4e38f; }
            else         { if (lane == ci - 32) v1 = -3.4e38f; }
        }
        if (lane == 0) {
            int row = blockIdx.x * 64 + rr;
            float mmax = vals[0];
            float e0 = expf(vals[0] - mmax), e1 = expf(vals[1] - mmax);
            float e2 = expf(vals[2] - mmax), e3 = expf(vals[3] - mmax);
            float inv = 1.0f / (e0 + e1 + e2 + e3);
            float* ow = out + OFF_W + (size_t)row * 4;
            float* oi = out + OFF_I + (size_t)row * 4;
            ow[0] = e0 * inv; ow[1] = e1 * inv; ow[2] = e2 * inv; ow[3] = e3 * inv;
            oi[0] = (float)ids[0]; oi[1] = (float)ids[1];
            oi[2] = (float)ids[2]; oi[3] = (float)ids[3];
        }
    }
}

// ---------------------------------------------------------------------------
// K2: mask writer. 2048 blocks x 4 q-rows, interval predicates, plain stores.
// ---------------------------------------------------------------------------
__global__ __launch_bounds__(256) void mask_kernel(float* __restrict__ out) {
    int mb = blockIdx.x;                    // 0 .. 2047
    int b  = mb >> 10;
    int q0 = (mb & 1023) << 2;
    int tid = threadIdx.x;

    float* fullb = out + (size_t)b * S * S;
    float* slidb = out + OFF_SLID + (size_t)b * S * S;

    #pragma unroll
    for (int qi = 0; qi < 4; qi++) {
        int q = q0 + qi;
        int4 mt = g_qmeta[b * S + q];       // {flo, s1lo, v2lo, v2hi}
        int flo = mt.x, slo = mt.y, vlo = mt.z;
        unsigned vspan = (unsigned)(mt.w - mt.z);
        float4* fo = (float4*)(fullb + (size_t)q * S);
        float4* so = (float4*)(slidb + (size_t)q * S);
        #pragma unroll
        for (int it = 0; it < 4; it++) {
            int k4 = tid + it * 256;
            int kv = k4 * 4;
            float4 f, sl;
            #pragma unroll
            for (int j = 0; j < 4; j++) {
                int k = kv + j;
                bool fb = (k >= flo) & (k <= q);
                bool sb = ((k >= slo) & (k <= q)) | ((unsigned)(k - vlo) <= vspan);
                (&f.x)[j]  = fb ? 0.0f : NEGF;
                (&sl.x)[j] = sb ? 0.0f : NEGF;
            }
            fo[k4] = f;
            so[k4] = sl;
        }
    }
}

// ---------------------------------------------------------------------------
extern "C" void kernel_launch(void* const* d_in, const int* in_sizes, int n_in,
                              void* d_out, int out_size) {
    const float* x      = (const float*)d_in[0];
    const int*   packed = (const int*)d_in[1];
    const int*   mm     = (const int*)d_in[2];
    const float* scale  = (const float*)d_in[3];
    const float* pw     = (const float*)d_in[4];
    float* out = (float*)d_out;

    static int smem_set = 0;
    if (!smem_set) {
        cudaFuncSetAttribute(gate_mma_kernel,
                             cudaFuncAttributeMaxDynamicSharedMemorySize,
                             GATE_SMEM_BYTES);
        smem_set = 1;
    }

    foldprep_kernel<<<FOLD_BLOCKS + B, 256>>>(scale, pw, packed, mm);
    gate_mma_kernel<<<GATE_BLOCKS, 256, GATE_SMEM_BYTES>>>(x, out);
    mask_kernel<<<2048, 256>>>(out);
}

// round 17
// speedup vs baseline: 1.8739x; 1.0188x over previous
#include <cuda_runtime.h>
#include <cuda_fp16.h>
#include <math.h>
#include <stdint.h>

#define H 2048
#define E 64
#define S 4096
#define B 2
#define SW 1024
#define NEGF (-3.4028234663852886e38f)   // -FLT_MAX == finfo(float32).min

#define OFF_SLID 33554432ull             // 2*4096*4096
#define OFF_W    67108864ull
#define OFF_I    67141632ull             // OFF_W + 8192*4

#define RSQRT_H 0.022097086912079608f    // 1/sqrt(2048)
#define GATE_BLOCKS 128                  // 64 rows per block
#define NC (H / 16)                      // 128 k16-chunks

// gate epilogue dynamic smem: sml[4][64][68] + ssqs[4][64]
#define SML_F (4 * 64 * 68)
#define GATE_SMEM_BYTES ((SML_F + 4 * 64) * 4)

// scale both operands by 256 (keeps fp16 "mid" splits in normal range);
// compensate exactly with 2^-16 folded into the rmsnorm multiplier.
#define OPSCALE 256.0f
#define INV_SCALE2 (1.0f / 65536.0f)

// scratch (no allocations allowed)
__device__ int4 g_qmeta[B * S];                         // {flo, s1lo, v2lo, v2hi}
__device__ __align__(16) unsigned g_wfmt[NC * 8 * 32 * 4];  // {wh0,wh1,wm0,wm1}

// ---------------------------------------------------------------------------
// fp16 2-way split of a (pre-scaled) fp32 pair: f = hi + mid + O(2^-22 f)
// ---------------------------------------------------------------------------
__device__ __forceinline__ void split_f16(float a, float b, unsigned& hi,
                                          unsigned& mid) {
    __half2 h = __float22half2_rn(make_float2(a, b));
    float2 hb = __half22float2(h);
    __half2 m = __float22half2_rn(make_float2(a - hb.x, b - hb.y));
    hi  = *(unsigned*)&h;
    mid = *(unsigned*)&m;
}

__device__ __forceinline__ void mma16816(float* c, const unsigned* a,
                                         unsigned b0, unsigned b1) {
    asm("mma.sync.aligned.m16n8k16.row.col.f32.f16.f16.f32 "
        "{%0,%1,%2,%3}, {%4,%5,%6,%7}, {%8,%9}, {%0,%1,%2,%3};"
        : "+f"(c[0]), "+f"(c[1]), "+f"(c[2]), "+f"(c[3])
        : "r"(a[0]), "r"(a[1]), "r"(a[2]), "r"(a[3]), "r"(b0), "r"(b1));
}

// ---------------------------------------------------------------------------
// block scans for prep (256 threads)
// ---------------------------------------------------------------------------
__device__ __forceinline__ int blk_excl_max(int agg, int t, int* sc) {
    int lane = t & 31, w = t >> 5;
    int inc = agg;
    #pragma unroll
    for (int o = 1; o < 32; o <<= 1) {
        int u = __shfl_up_sync(0xffffffffu, inc, o);
        if (lane >= o) inc = max(inc, u);
    }
    if (lane == 31) sc[w] = inc;
    __syncthreads();
    int wex = -0x7fffffff;
    for (int i = 0; i < w; i++) wex = max(wex, sc[i]);
    int lex = __shfl_up_sync(0xffffffffu, inc, 1);
    if (lane == 0) lex = -0x7fffffff;
    __syncthreads();
    return max(wex, lex);
}
__device__ __forceinline__ int blk_excl_min_bwd(int agg, int t, int* sc) {
    int lane = t & 31, w = t >> 5;
    int inc = agg;
    #pragma unroll
    for (int o = 1; o < 32; o <<= 1) {
        int u = __shfl_down_sync(0xffffffffu, inc, o);
        if (lane < 32 - o) inc = min(inc, u);
    }
    if (lane == 0) sc[w] = inc;
    __syncthreads();
    int wex = 0x7fffffff;
    for (int i = w + 1; i < 8; i++) wex = min(wex, sc[i]);
    int lex = __shfl_down_sync(0xffffffffu, inc, 1);
    if (lane == 31) lex = 0x7fffffff;
    __syncthreads();
    return min(wex, lex);
}

// ---------------------------------------------------------------------------
// K0: fold W (scale, H^-0.5, x256) -> fp16 2-way split B-fragment images.
// 256 blocks x 256 thr, 2 elems (one reg-pair) per thread: streaming, wide.
// B frag (m16n8k16, col): thread t (g=t>>2 = n, tg=t&3):
//   reg0 = {B[2tg][g], B[2tg+1][g]}, reg1 = {B[2tg+8][g], B[2tg+9][g]}
// ---------------------------------------------------------------------------
__global__ __launch_bounds__(256) void fold_kernel(const float* __restrict__ scale,
                                                   const float* __restrict__ pw) {
    int i = (blockIdx.x * 256 + threadIdx.x) * 2;        // over E*H = 131072
    float2 pw2 = *(const float2*)(pw + i);
    float2 sc2 = *(const float2*)(scale + (i & (H - 1)));
    const float K = RSQRT_H * OPSCALE;
    float v0 = pw2.x * sc2.x * K;
    float v1 = pw2.y * sc2.y * K;
    int e  = i >> 11;
    int h  = i & (H - 1);
    int c  = h >> 4, kk = h & 15;                        // kk even
    int nt = e >> 3, g = e & 7;
    unsigned hi, mid;
    split_f16(v0, v1, hi, mid);
    int R  = kk >> 3;
    int tg = (kk & 7) >> 1;
    int t  = g * 4 + tg;
    size_t b1 = ((size_t)(c * 8 + nt) * 32 + t) * 4;
    g_wfmt[b1 + R]     = hi;
    g_wfmt[b1 + 2 + R] = mid;
}

// ---------------------------------------------------------------------------
// K1: blocks [0,128): mma.sync gate (fp16 2-split, 3 products)
//     blocks [128,130): prep (mask interval metadata) on otherwise-idle SMs
// ---------------------------------------------------------------------------
__global__ __launch_bounds__(256) void gate_prep_kernel(const float* __restrict__ x,
                                                        const int* __restrict__ packed,
                                                        const int* __restrict__ mm,
                                                        float* __restrict__ out) {
    extern __shared__ float dsm[];
    int tid = threadIdx.x;

    if (blockIdx.x < GATE_BLOCKS) {
        // ================= GATE =================
        float (*sml)[64][68] = (float (*)[64][68])dsm;        // [q][row][expert]
        float (*ssqs)[64]    = (float (*)[64])(dsm + SML_F);  // [q][row]

        int w = tid >> 5, lane = tid & 31;
        int s = w >> 2, q = w & 3;
        int g = lane >> 2, tg = lane & 3;
        const float* xb = x + (size_t)blockIdx.x * 64 * H;
        int rowb = s * 32;

        float acc[2][8][4] = {};
        float ssq4[4] = {};          // [mt*2 + (0: row g, 1: row g+8)]

        for (int step = 0; step < 32; step++) {
            int c = q * 32 + step;
            int col = c * 16 + 2 * tg;
            unsigned Ah[2][4], Am[2][4];
            #pragma unroll
            for (int mt = 0; mt < 2; mt++) {
                const float* r0p = xb + (size_t)(rowb + mt * 16 + g) * H + col;
                const float* r1p = r0p + 8 * H;
                float2 p00 = *(const float2*)r0p;
                float2 p01 = *(const float2*)(r0p + 8);
                float2 p10 = *(const float2*)r1p;
                float2 p11 = *(const float2*)(r1p + 8);
                ssq4[mt*2+0] = fmaf(p00.x, p00.x, fmaf(p00.y, p00.y,
                                fmaf(p01.x, p01.x, fmaf(p01.y, p01.y, ssq4[mt*2+0]))));
                ssq4[mt*2+1] = fmaf(p10.x, p10.x, fmaf(p10.y, p10.y,
                                fmaf(p11.x, p11.x, fmaf(p11.y, p11.y, ssq4[mt*2+1]))));
                split_f16(p00.x * OPSCALE, p00.y * OPSCALE, Ah[mt][0], Am[mt][0]);
                split_f16(p10.x * OPSCALE, p10.y * OPSCALE, Ah[mt][1], Am[mt][1]);
                split_f16(p01.x * OPSCALE, p01.y * OPSCALE, Ah[mt][2], Am[mt][2]);
                split_f16(p11.x * OPSCALE, p11.y * OPSCALE, Ah[mt][3], Am[mt][3]);
            }
            #pragma unroll
            for (int nt = 0; nt < 8; nt++) {
                uint4 bA = *((const uint4*)g_wfmt + ((c * 8 + nt) * 32 + lane));
                #pragma unroll
                for (int mt = 0; mt < 2; mt++) {
                    mma16816(acc[mt][nt], Ah[mt], bA.x, bA.y);   // hi * hi
                    mma16816(acc[mt][nt], Ah[mt], bA.z, bA.w);   // hi * mid
                    mma16816(acc[mt][nt], Am[mt], bA.x, bA.y);   // mid * hi
                }
            }
        }

        // partial logits -> sml[q] (every slot written exactly once: no atomics)
        #pragma unroll
        for (int mt = 0; mt < 2; mt++) {
            int rl = rowb + mt * 16 + g;
            #pragma unroll
            for (int nt = 0; nt < 8; nt++) {
                int e0 = nt * 8 + 2 * tg;
                *(float2*)&sml[q][rl][e0]     = make_float2(acc[mt][nt][0], acc[mt][nt][1]);
                *(float2*)&sml[q][rl + 8][e0] = make_float2(acc[mt][nt][2], acc[mt][nt][3]);
            }
        }
        // ssq partials: quad-reduce over tg, lane tg==0 writes
        #pragma unroll
        for (int i = 0; i < 4; i++) {
            float v = ssq4[i];
            v += __shfl_xor_sync(0xffffffffu, v, 1);
            v += __shfl_xor_sync(0xffffffffu, v, 2);
            if (tg == 0) ssqs[q][rowb + (i >> 1) * 16 + g + (i & 1) * 8] = v;
        }
        __syncthreads();

        // top-4 + renormalized softmax: warp w handles rows 8w..8w+7
        #pragma unroll
        for (int i = 0; i < 8; i++) {
            int rr = w * 8 + i;
            float ssq = ssqs[0][rr] + ssqs[1][rr] + ssqs[2][rr] + ssqs[3][rr];
            float r = rsqrtf(ssq * (1.0f / H) + 1e-6f) * INV_SCALE2;
            float v0 = r * (sml[0][rr][lane] + sml[1][rr][lane]
                          + sml[2][rr][lane] + sml[3][rr][lane]);
            float v1 = r * (sml[0][rr][lane + 32] + sml[1][rr][lane + 32]
                          + sml[2][rr][lane + 32] + sml[3][rr][lane + 32]);
            float vals[4]; int ids[4];
            #pragma unroll
            for (int t4 = 0; t4 < 4; t4++) {
                float cv; int ci;
                if (v1 > v0) { cv = v1; ci = lane + 32; }
                else         { cv = v0; ci = lane; }   // tie -> smaller index
                #pragma unroll
                for (int o = 16; o; o >>= 1) {
                    float ov = __shfl_xor_sync(0xffffffffu, cv, o);
                    int   oi = __shfl_xor_sync(0xffffffffu, ci, o);
                    if (ov > cv || (ov == cv && oi < ci)) { cv = ov; ci = oi; }
                }
                vals[t4] = cv; ids[t4] = ci;
                if (ci < 32) { if (lane == ci)      v0 = -3.4e38f; }
                else         { if (lane == ci - 32) v1 = -3.4e38f; }
            }
            if (lane == 0) {
                int row = blockIdx.x * 64 + rr;
                float mmax = vals[0];
                float e0 = expf(vals[0] - mmax), e1 = expf(vals[1] - mmax);
                float e2 = expf(vals[2] - mmax), e3 = expf(vals[3] - mmax);
                float inv = 1.0f / (e0 + e1 + e2 + e3);
                float* ow = out + OFF_W + (size_t)row * 4;
                float* oi = out + OFF_I + (size_t)row * 4;
                ow[0] = e0 * inv; ow[1] = e1 * inv; ow[2] = e2 * inv; ow[3] = e3 * inv;
                oi[0] = (float)ids[0]; oi[1] = (float)ids[1];
                oi[2] = (float)ids[2]; oi[3] = (float)ids[3];
            }
        }
    } else {
        // ================= PREP =================
        __shared__ int sc[8];
        const int INF = 0x7fffffff;
        int b = blockIdx.x - GATE_BLOCKS;
        int t = tid;
        int base = t * 16;
        const int* pk = packed + b * S;
        const int* m  = mm + b * S;

        int p[16]; bool v[16];
        #pragma unroll
        for (int c4 = 0; c4 < 4; c4++) {
            int4 pp4 = ((const int4*)(pk + base))[c4];
            int4 mm4 = ((const int4*)(m + base))[c4];
            p[4*c4+0] = pp4.x; p[4*c4+1] = pp4.y; p[4*c4+2] = pp4.z; p[4*c4+3] = pp4.w;
            v[4*c4+0] = (mm4.x == 1) | (mm4.x == 2);
            v[4*c4+1] = (mm4.y == 1) | (mm4.y == 2);
            v[4*c4+2] = (mm4.z == 1) | (mm4.z == 2);
            v[4*c4+3] = (mm4.w == 1) | (mm4.w == 2);
        }
        int  pprev = (base > 0) ? pk[base - 1] : -123456;
        int  pnext = (base + 16 < S) ? pk[base + 16] : -123456;
        int  mprev = (base > 0) ? m[base - 1] : 0;
        int  mnext = (base + 16 < S) ? m[base + 16] : 0;
        bool vprev = (mprev == 1) | (mprev == 2);
        bool vnext = (mnext == 1) | (mnext == 2);

        int dloc[16];
        {
            int run = -1, pp = pprev;
            #pragma unroll
            for (int j = 0; j < 16; j++) {
                if (p[j] != pp) run = base + j;
                dloc[j] = run; pp = p[j];
            }
            int ex = blk_excl_max(run, t, sc);
            #pragma unroll
            for (int j = 0; j < 16; j++) if (ex > dloc[j]) dloc[j] = ex;
        }
        int vloc[16];
        {
            int run = -1; bool pv = vprev;
            #pragma unroll
            for (int j = 0; j < 16; j++) {
                if (v[j] && !pv) run = base + j;
                vloc[j] = run; pv = v[j];
            }
            int ex = blk_excl_max(run, t, sc);
            #pragma unroll
            for (int j = 0; j < 16; j++) if (ex > vloc[j]) vloc[j] = ex;
        }
        int dend[16];
        {
            int run = INF, np = pnext;
            #pragma unroll
            for (int jj = 15; jj >= 0; jj--) {
                if (p[jj] != np) run = base + jj;
                dend[jj] = run; np = p[jj];
            }
            int ex = blk_excl_min_bwd(run, t, sc);
            #pragma unroll
            for (int j = 0; j < 16; j++) if (ex < dend[j]) dend[j] = ex;
        }
        int vend[16];
        {
            int run = INF; bool nv = vnext;
            #pragma unroll
            for (int jj = 15; jj >= 0; jj--) {
                if (v[jj] && !nv) run = base + jj;
                vend[jj] = run; nv = v[jj];
            }
            int ex = blk_excl_min_bwd(run, t, sc);
            #pragma unroll
            for (int j = 0; j < 16; j++) if (ex < vend[j]) vend[j] = ex;
        }

        #pragma unroll
        for (int j = 0; j < 16; j++) {
            int q = base + j;
            int4 mt;
            if (p[j] <= 0) {
                mt.x = S; mt.y = S; mt.z = S; mt.w = -1;
            } else {
                int flo = dloc[j];
                mt.x = flo;
                int s1 = q - (SW - 1);
                mt.y = (s1 > flo) ? s1 : flo;
                if (v[j]) {
                    int vl = vloc[j]; if (flo > vl) vl = flo;
                    int vh = vend[j]; if (dend[j] < vh) vh = dend[j];
                    mt.z = vl; mt.w = vh;
                } else {
                    mt.z = S; mt.w = -1;
                }
            }
            g_qmeta[b * S + q] = mt;
        }
    }
}

// ---------------------------------------------------------------------------
// K2: mask writer. 4096 blocks x 2 q-rows, interval predicates, plain stores.
// ---------------------------------------------------------------------------
__global__ __launch_bounds__(256) void mask_kernel(float* __restrict__ out) {
    int mb = blockIdx.x;                    // 0 .. 4095
    int b  = mb >> 11;
    int q0 = (mb & 2047) << 1;
    int tid = threadIdx.x;

    float* fullb = out + (size_t)b * S * S;
    float* slidb = out + OFF_SLID + (size_t)b * S * S;

    #pragma unroll
    for (int qi = 0; qi < 2; qi++) {
        int q = q0 + qi;
        int4 mt = g_qmeta[b * S + q];       // {flo, s1lo, v2lo, v2hi}
        int flo = mt.x, slo = mt.y, vlo = mt.z;
        unsigned vspan = (unsigned)(mt.w - mt.z);
        float4* fo = (float4*)(fullb + (size_t)q * S);
        float4* so = (float4*)(slidb + (size_t)q * S);
        #pragma unroll
        for (int it = 0; it < 4; it++) {
            int k4 = tid + it * 256;
            int kv = k4 * 4;
            float4 f, sl;
            #pragma unroll
            for (int j = 0; j < 4; j++) {
                int k = kv + j;
                bool fb = (k >= flo) & (k <= q);
                bool sb = ((k >= slo) & (k <= q)) | ((unsigned)(k - vlo) <= vspan);
                (&f.x)[j]  = fb ? 0.0f : NEGF;
                (&sl.x)[j] = sb ? 0.0f : NEGF;
            }
            fo[k4] = f;
            so[k4] = sl;
        }
    }
}

// ---------------------------------------------------------------------------
extern "C" void kernel_launch(void* const* d_in, const int* in_sizes, int n_in,
                              void* d_out, int out_size) {
    const float* x      = (const float*)d_in[0];
    const int*   packed = (const int*)d_in[1];
    const int*   mm     = (const int*)d_in[2];
    const float* scale  = (const float*)d_in[3];
    const float* pw     = (const float*)d_in[4];
    float* out = (float*)d_out;

    static int smem_set = 0;
    if (!smem_set) {
        cudaFuncSetAttribute(gate_prep_kernel,
                             cudaFuncAttributeMaxDynamicSharedMemorySize,
                             GATE_SMEM_BYTES);
        smem_set = 1;
    }

    fold_kernel<<<256, 256>>>(scale, pw);
    gate_prep_kernel<<<GATE_BLOCKS + B, 256, GATE_SMEM_BYTES>>>(x, packed, mm, out);
    mask_kernel<<<4096, 256>>>(out);
}